// round 3
// baseline (speedup 1.0000x reference)
#include <cuda_runtime.h>
#include <math.h>

// Problem constants
constexpr int B_   = 4;
constexpr int C_   = 192;
constexpr int H_   = 192;
constexpr int W_   = 192;
constexpr int NPIX = H_ * W_;       // 36864
constexpr int HEADS = 6;
constexpr int CPH   = 32;           // channels per head

// Scratch layout (floats)
constexpr long long KV_SZ  = (long long)B_ * 2 * C_ * NPIX;  // 56,623,104
constexpr long long Q_SZ   = (long long)B_ * C_ * NPIX;      // 28,311,552
constexpr long long KV_OFF  = 0;
constexpr long long KV2_OFF = KV_OFF + KV_SZ;
constexpr long long Q_OFF   = KV2_OFF + KV_SZ;
constexpr long long G_OFF   = Q_OFF + Q_SZ;                   // 24*1024
constexpr long long A_OFF   = G_OFF + (long long)B_*HEADS*CPH*CPH;
constexpr long long NQ_OFF  = A_OFF + (long long)B_*HEADS*CPH*CPH;
constexpr long long NK_OFF  = NQ_OFF + (long long)B_*C_;
constexpr long long M_OFF   = NK_OFF + (long long)B_*C_;
constexpr long long TOTAL   = M_OFF + (long long)B_*C_*C_;

__device__ float g_scratch[TOTAL];

// ---------------------------------------------------------------------------
// Generic tiled SGEMM: C[M,N] = A[M,K] (row-major) * B[K,N] (row-major, ld=N)
// im2col mode: B is x[b] with layout [C_][NPIX]; K = C_*9; logical
//   B[(ci*9 + kh*3 + kw)][p] = x[ci][(h+kh-1)*W + (w+kw-1)] (zero-padded)
// Pointers may come from harness (ext != nullptr) or scratch (offset).
// blockIdx.z = batch; per-batch strides sA/sB/sC.
// ---------------------------------------------------------------------------
constexpr int BM = 128, BN = 64, BK = 8;

__global__ void sgemm(const float* __restrict__ Aext, long long offA, long long sA,
                      const float* __restrict__ Bext, long long offB, long long sB,
                      float*       __restrict__ Cext, long long offC, long long sC,
                      int M, int N, int K, int im2col)
{
    int b = blockIdx.z;
    const float* A  = (Aext ? Aext : g_scratch + offA) + (long long)b * sA;
    const float* Bp = (Bext ? Bext : g_scratch + offB) + (long long)b * sB;
    float*       Cp = (Cext ? Cext : g_scratch + offC) + (long long)b * sC;

    __shared__ float As[BK][136];   // padded: conflict-light, 16B-aligned rows
    __shared__ float Bs[BK][BN];

    int tid = threadIdx.x;          // 256 threads
    int tx = tid & 15;              // 16 cols of threads, 4 outputs each
    int ty = tid >> 4;              // 16 rows of threads, 8 outputs each
    int m0 = blockIdx.y * BM;
    int n0 = blockIdx.x * BN;

    float acc[8][4];
#pragma unroll
    for (int i = 0; i < 8; i++)
#pragma unroll
        for (int j = 0; j < 4; j++) acc[i][j] = 0.f;

    for (int k0 = 0; k0 < K; k0 += BK) {
        // Load A tile (BMxBK) transposed into As[k][m]
#pragma unroll
        for (int p = 0; p < 4; p++) {
            int r  = (tid >> 3) + p * 32;
            int kk = tid & 7;
            int m  = m0 + r;
            As[kk][r] = (m < M) ? A[(long long)m * K + k0 + kk] : 0.f;
        }
        // Load B tile (BKxBN)
#pragma unroll
        for (int p = 0; p < 2; p++) {
            int idx = tid + p * 256;
            int kk = idx >> 6;
            int nn = idx & 63;
            int kg = k0 + kk;
            int n  = n0 + nn;
            float v;
            if (!im2col) {
                v = Bp[(long long)kg * N + n];
            } else {
                int ci = kg / 9;
                int r9 = kg - ci * 9;
                int kh = r9 / 3;
                int kw = r9 - kh * 3;
                int h = n / W_;
                int w = n - h * W_;
                int hs = h + kh - 1;
                int ws = w + kw - 1;
                v = (hs >= 0 && hs < H_ && ws >= 0 && ws < W_)
                        ? Bp[(long long)ci * NPIX + hs * W_ + ws] : 0.f;
            }
            Bs[kk][nn] = v;
        }
        __syncthreads();

#pragma unroll
        for (int kk = 0; kk < BK; kk++) {
            float a[8], bb[4];
#pragma unroll
            for (int i = 0; i < 8; i++) a[i] = As[kk][ty * 8 + i];
#pragma unroll
            for (int j = 0; j < 4; j++) bb[j] = Bs[kk][tx * 4 + j];
#pragma unroll
            for (int i = 0; i < 8; i++)
#pragma unroll
                for (int j = 0; j < 4; j++) acc[i][j] += a[i] * bb[j];
        }
        __syncthreads();
    }

#pragma unroll
    for (int i = 0; i < 8; i++) {
        int m = m0 + ty * 8 + i;
        if (m < M) {
#pragma unroll
            for (int j = 0; j < 4; j++)
                Cp[(long long)m * N + n0 + tx * 4 + j] = acc[i][j];
        }
    }
}

// ---------------------------------------------------------------------------
// Depthwise 3x3 SAME on kv -> kv2.  grid: (1, H_, B_*2C_), block: W_ threads.
// ---------------------------------------------------------------------------
__global__ void dwconv(const float* __restrict__ wdw)
{
    int bc = blockIdx.z;                    // b * 2C + ch
    int ch = bc % (2 * C_);
    int h  = blockIdx.y;
    int w  = threadIdx.x;
    const float* src = g_scratch + KV_OFF  + (long long)bc * NPIX;
    float*       dst = g_scratch + KV2_OFF + (long long)bc * NPIX;

    float wv[9];
#pragma unroll
    for (int i = 0; i < 9; i++) wv[i] = __ldg(&wdw[ch * 9 + i]);

    float acc = 0.f;
#pragma unroll
    for (int kh = 0; kh < 3; kh++) {
        int hs = h + kh - 1;
        if (hs < 0 || hs >= H_) continue;
#pragma unroll
        for (int kw = 0; kw < 3; kw++) {
            int ws = w + kw - 1;
            if (ws < 0 || ws >= W_) continue;
            acc += wv[kh * 3 + kw] * src[hs * W_ + ws];
        }
    }
    dst[h * W_ + w] = acc;
}

// ---------------------------------------------------------------------------
// Row sum-of-squares -> clamped L2 norms for q and k.
// grid: 2*B_*C_ blocks of 256. First half = q rows, second half = k rows.
// ---------------------------------------------------------------------------
__global__ void sumsq()
{
    int row = blockIdx.x;
    int isK = row >= B_ * C_;
    int r   = row - isK * (B_ * C_);        // [0, B_*C_)
    int b   = r / C_;
    int ch  = r - b * C_;
    const float* src = isK
        ? (g_scratch + KV2_OFF + ((long long)b * 2 * C_ + ch) * NPIX)   // k half
        : (g_scratch + Q_OFF   + ((long long)b * C_ + ch) * NPIX);

    float s = 0.f;
    for (int i = threadIdx.x; i < NPIX; i += 256) {
        float v = src[i];
        s += v * v;
    }
    __shared__ float red[256];
    red[threadIdx.x] = s;
    __syncthreads();
    for (int st = 128; st > 0; st >>= 1) {
        if (threadIdx.x < st) red[threadIdx.x] += red[threadIdx.x + st];
        __syncthreads();
    }
    if (threadIdx.x == 0) {
        float denom = fmaxf(sqrtf(red[0]), 1e-12f);
        g_scratch[(isK ? NK_OFF : NQ_OFF) + r] = denom;
    }
}

__global__ void zeroG()
{
    g_scratch[G_OFF + (long long)blockIdx.x * 1024 + threadIdx.x] = 0.f;
}

// ---------------------------------------------------------------------------
// Gram matrices: G[b,h][c][d] = sum_n q[b,h*32+c,n] * k[b,h*32+d,n]
// grid: (NPIX/1024, B_*HEADS), block: 1024 (thread = c*32+d). atomicAdd partials.
// ---------------------------------------------------------------------------
__global__ void gram()
{
    int bh = blockIdx.y;
    int b  = bh / HEADS;
    int hh = bh - b * HEADS;
    long long qbase = Q_OFF   + ((long long)b * C_     + hh * CPH) * NPIX;
    long long kbase = KV2_OFF + ((long long)b * 2 * C_ + hh * CPH) * NPIX;
    int n0 = blockIdx.x * 1024;

    __shared__ float qs[CPH][33], ks[CPH][33];
    int tid = threadIdx.x;
    int c = tid >> 5, d = tid & 31;

    float acc = 0.f;
    for (int t = 0; t < 1024; t += 32) {
        qs[c][d] = g_scratch[qbase + (long long)c * NPIX + n0 + t + d];
        ks[c][d] = g_scratch[kbase + (long long)c * NPIX + n0 + t + d];
        __syncthreads();
#pragma unroll
        for (int j = 0; j < 32; j++) acc += qs[c][j] * ks[d][j];
        __syncthreads();
    }
    atomicAdd(&g_scratch[G_OFF + (long long)bh * 1024 + tid], acc);
}

// ---------------------------------------------------------------------------
// Normalize by L2 norms, apply temperature, softmax over d -> A[b,h][c][d].
// grid: B_*HEADS blocks, 32 threads (one per row c).
// ---------------------------------------------------------------------------
__global__ void softmaxA(const float* __restrict__ temp)
{
    int bh = blockIdx.x;
    int b  = bh / HEADS;
    int hh = bh - b * HEADS;
    int c  = threadIdx.x;

    const float* G = g_scratch + G_OFF + (long long)bh * 1024;
    float*       A = g_scratch + A_OFF + (long long)bh * 1024;
    float nq = g_scratch[NQ_OFF + b * C_ + hh * CPH + c];
    float t  = __ldg(&temp[hh]);

    float row[32];
    float mx = -1e30f;
#pragma unroll
    for (int d = 0; d < 32; d++) {
        float nk = g_scratch[NK_OFF + b * C_ + hh * CPH + d];
        float v = G[c * 32 + d] / (nq * nk) * t;
        row[d] = v;
        mx = fmaxf(mx, v);
    }
    float sum = 0.f;
#pragma unroll
    for (int d = 0; d < 32; d++) {
        row[d] = __expf(row[d] - mx);
        sum += row[d];
    }
    float inv = 1.f / sum;
#pragma unroll
    for (int d = 0; d < 32; d++) A[c * 32 + d] = row[d] * inv;
}

// ---------------------------------------------------------------------------
// M_b = proj_w @ blockdiag(A_b):  M[b][co][h*32+d] = sum_c P[co][h*32+c]*A[b,h][c][d]
// grid: B_ blocks, C_ threads (one per co).
// ---------------------------------------------------------------------------
__global__ void buildM(const float* __restrict__ projw)
{
    int b  = blockIdx.x;
    int co = threadIdx.x;
    __shared__ float As_[HEADS * CPH * CPH];    // 24 KB
    for (int i = co; i < HEADS * CPH * CPH; i += C_)
        As_[i] = g_scratch[A_OFF + (long long)b * HEADS * CPH * CPH + i];
    __syncthreads();

    for (int hh = 0; hh < HEADS; hh++) {
        float p[CPH];
#pragma unroll
        for (int c = 0; c < CPH; c++) p[c] = __ldg(&projw[co * C_ + hh * CPH + c]);
        for (int d = 0; d < CPH; d++) {
            float s = 0.f;
#pragma unroll
            for (int c = 0; c < CPH; c++)
                s += p[c] * As_[hh * CPH * CPH + c * CPH + d];
            g_scratch[M_OFF + ((long long)b * C_ + co) * C_ + hh * CPH + d] = s;
        }
    }
}

// ---------------------------------------------------------------------------
extern "C" void kernel_launch(void* const* d_in, const int* in_sizes, int n_in,
                              void* d_out, int out_size)
{
    const float* x      = (const float*)d_in[0];
    const float* y      = (const float*)d_in[1];
    const float* q_w    = (const float*)d_in[2];
    const float* kv_w   = (const float*)d_in[3];
    const float* kvdw_w = (const float*)d_in[4];
    const float* proj_w = (const float*)d_in[5];
    const float* temp   = (const float*)d_in[6];
    float* out = (float*)d_out;

    (void)in_sizes; (void)n_in; (void)out_size;

    // 0) zero Gram accumulators
    zeroG<<<B_ * HEADS, 1024>>>();

    // 1) kv = 1x1 conv(y): GEMM [384 x 192] * [192 x N] per batch
    sgemm<<<dim3(NPIX / BN, (2 * C_ + BM - 1) / BM, B_), 256>>>(
        kv_w, 0, 0,
        y, 0, (long long)C_ * NPIX,
        nullptr, KV_OFF, (long long)2 * C_ * NPIX,
        2 * C_, NPIX, C_, 0);

    // 2) depthwise 3x3 on kv -> kv2
    dwconv<<<dim3(1, H_, B_ * 2 * C_), W_>>>(kvdw_w);

    // 3) q = 3x3 conv(x): implicit GEMM [192 x 1728] * im2col(x) per batch
    sgemm<<<dim3(NPIX / BN, (C_ + BM - 1) / BM, B_), 256>>>(
        q_w, 0, 0,
        x, 0, (long long)C_ * NPIX,
        nullptr, Q_OFF, (long long)C_ * NPIX,
        C_, NPIX, C_ * 9, 1);

    // 4) L2 norms of q rows and k rows
    sumsq<<<2 * B_ * C_, 256>>>();

    // 5) Gram matrices q·k^T per (b, head)
    gram<<<dim3(NPIX / 1024, B_ * HEADS), 1024>>>();

    // 6) normalize + temperature + softmax
    softmaxA<<<B_ * HEADS, CPH>>>(temp);

    // 7) M_b = proj_w @ blockdiag(A_b)
    buildM<<<B_, C_>>>(proj_w);

    // 8) out = M_b @ v_b  (fused attn@v + 1x1 proj)
    sgemm<<<dim3(NPIX / BN, (C_ + BM - 1) / BM, B_), 256>>>(
        nullptr, M_OFF, (long long)C_ * C_,
        nullptr, KV2_OFF + (long long)C_ * NPIX, (long long)2 * C_ * NPIX,
        out, 0, (long long)C_ * NPIX,
        C_, NPIX, C_, 0);
}

// round 6
// speedup vs baseline: 1.7737x; 1.7737x over previous
#include <cuda_runtime.h>
#include <cuda_bf16.h>
#include <cstdint>
#include <math.h>

// ============================ problem constants =============================
constexpr int B_ = 4, C_ = 192, H_ = 192, W_ = 192;
constexpr int NPIX = H_ * W_;          // 36864
constexpr int HEADS = 6, CPH = 32;

// ============================ fp32 scratch ==================================
constexpr long long KV_OFF = 0;                                       // [B][2C][NPIX]
constexpr long long K2_OFF = KV_OFF + (long long)B_ * 2 * C_ * NPIX;  // k half [B][C][NPIX]
constexpr long long Q_OFF  = K2_OFF + (long long)B_ * C_ * NPIX;      // q [B][C][NPIX]
constexpr long long G_OFF  = Q_OFF  + (long long)B_ * C_ * NPIX;      // gram [24][1024]
constexpr long long AT_OFF = G_OFF  + B_ * HEADS * CPH * CPH;         // attn [24][1024]
constexpr long long NQ_OFF = AT_OFF + B_ * HEADS * CPH * CPH;
constexpr long long NK_OFF = NQ_OFF + B_ * C_;
constexpr long long FTOT   = NK_OFF + B_ * C_;
__device__ float g_f[FTOT];

// ============================ bf16 scratch ==================================
constexpr long long SACT = (long long)B_ * C_ * NPIX;   // 28,311,552
constexpr long long XH = 0,        XL = XH + SACT;
constexpr long long YH = XL + SACT, YL = YH + SACT;
constexpr long long VH = YL + SACT, VL = VH + SACT;
constexpr long long QWH  = VL + SACT;            // [9][192][192]
constexpr long long QWL  = QWH + 192 * 1728;
constexpr long long KVWH = QWL + 192 * 1728;     // [384][192]
constexpr long long KVWL = KVWH + 384 * 192;
constexpr long long MWH  = KVWL + 384 * 192;     // [B][192][192]
constexpr long long MWL  = MWH + (long long)B_ * C_ * C_;
constexpr long long HTOT = MWL + (long long)B_ * C_ * C_;
__device__ __align__(256) __nv_bfloat16 g_h[HTOT];

// ============================ warp MMA GEMM =================================
// D[128 pix, 64 out] = sum_taps sum_k A[b, k, pix+shift(tap)] * W[tap, out, k]
// A split hi/lo bf16 [B][192][NPIX]; W split hi/lo bf16 [tap][outTot][192].
// mma.sync m16n8k16 bf16 (baseline PTX, runs on tensor pipe as HMMA).
//
// smem: per stage  A (hi+lo) 128x32 rows padded to 80B,  B (hi+lo) 64x32.
constexpr int ROWB  = 80;                       // 32*2 + 16 pad (keeps 16B align)
constexpr int S_AH = 0;
constexpr int S_AL = S_AH + 128 * ROWB;         // 10240
constexpr int S_BH = S_AL + 128 * ROWB;         // 20480
constexpr int S_BL = S_BH + 64 * ROWB;          // 25600
constexpr int STAGE = S_BL + 64 * ROWB;         // 30720
constexpr int SMEM_TOTAL = 2 * STAGE;           // 61440

// swizzled byte offset of element (row r, col k) inside a tile
__device__ __forceinline__ uint32_t sw_off(int r, int k) {
    int kk = (k + (((r >> 3) & 3) << 3)) & 31;  // rotate k by 8*((r>>3)&3)
    return (uint32_t)(r * ROWB + kk * 2);
}
__device__ __forceinline__ uint32_t lds32(const char* base, int r, int k) {
    return *(const uint32_t*)(base + sw_off(r, k));
}

#define MMA16816(d, a, bb) \
    asm volatile("mma.sync.aligned.m16n8k16.row.col.f32.bf16.bf16.f32 " \
                 "{%0,%1,%2,%3}, {%4,%5,%6,%7}, {%8,%9}, {%0,%1,%2,%3};" \
                 : "+f"((d)[0]), "+f"((d)[1]), "+f"((d)[2]), "+f"((d)[3]) \
                 : "r"((a)[0]), "r"((a)[1]), "r"((a)[2]), "r"((a)[3]), \
                   "r"((bb)[0]), "r"((bb)[1]))

__global__ void __launch_bounds__(256) hgemm(
    const __nv_bfloat16* __restrict__ Ahi, const __nv_bfloat16* __restrict__ Alo,
    const __nv_bfloat16* __restrict__ Whi, const __nv_bfloat16* __restrict__ Wlo,
    long long wBatchStride,
    float* __restrict__ Out, long long outBatchStride,
    int outTot, int Kpt, int ntaps)
{
    extern __shared__ char smem[];
    const int tid  = threadIdx.x;
    const int lane = tid & 31, wid = tid >> 5;
    const int wm = wid & 3, wn = wid >> 2;       // warp grid 4(m) x 2(n)
    const int lq = lane >> 2, lk2 = (lane & 3) * 2;

    const int n0   = blockIdx.x * 64;            // out-channel block (fast idx: L2 A reuse)
    const int pix0 = blockIdx.y * 128;
    const int b    = blockIdx.z;

    // loader mapping
    const int pixl = tid & 127;
    const int kb   = (tid >> 7) * 16;            // 0 or 16
    const int pg   = pix0 + pixl;
    const int ph   = pg / W_, pw = pg - ph * W_;
    const long long abatch = (long long)b * Kpt * NPIX;   // Kpt==192 channels
    const int bn = tid >> 2;                     // B-tile row (0..63)
    const int bkq = (tid & 3) * 8;               // B-tile k quad

    const int kcPerTap = Kpt >> 5;               // chunks of 32 per tap
    const int nchunks  = ntaps * kcPerTap;

    float acc[2][4][4];
#pragma unroll
    for (int i = 0; i < 2; i++)
#pragma unroll
        for (int j = 0; j < 4; j++)
#pragma unroll
            for (int r = 0; r < 4; r++) acc[i][j][r] = 0.f;

    auto load_stage = [&](int c, int buf) {
        int tap = c / kcPerTap;
        int kc  = c - tap * kcPerTap;
        int dh = 0, dw = 0;
        if (ntaps > 1) { dh = tap / 3 - 1; dw = tap - (tap / 3) * 3 - 1; }
        const int  soff  = dh * W_ + dw;
        const bool valid = ((unsigned)(ph + dh) < (unsigned)H_) &&
                           ((unsigned)(pw + dw) < (unsigned)W_);
        const int k0 = kc * 32;
        char* sb = smem + buf * STAGE;

        // ---- A tile (hi+lo): smem [pix][k], gmem [k][pix] ----
        const long long gA = abatch + (long long)(k0 + kb) * NPIX + pg + soff;
        const unsigned short* pH = (const unsigned short*)(Ahi) + gA;
        const unsigned short* pL = (const unsigned short*)(Alo) + gA;
#pragma unroll
        for (int i = 0; i < 16; i++) {
            uint32_t so = sw_off(pixl, kb + i);
            unsigned short hv = valid ? pH[(long long)i * NPIX] : (unsigned short)0;
            unsigned short lv = valid ? pL[(long long)i * NPIX] : (unsigned short)0;
            *(unsigned short*)(sb + S_AH + so) = hv;
            *(unsigned short*)(sb + S_AL + so) = lv;
        }
        // ---- B tile (hi+lo): smem [n][k], gmem row-major [.., k] ----
        {
            long long off = (long long)b * wBatchStride +
                            ((long long)tap * outTot + n0 + bn) * Kpt + k0 + bkq;
            uint32_t so = sw_off(bn, bkq);       // 16B-aligned (bkq mult of 8)
            *(uint4*)(sb + S_BH + so) = *(const uint4*)(Whi + off);
            *(uint4*)(sb + S_BL + so) = *(const uint4*)(Wlo + off);
        }
    };

    load_stage(0, 0);
    __syncthreads();

    for (int c = 0; c < nchunks; c++) {
        if (c + 1 < nchunks) load_stage(c + 1, (c + 1) & 1);

        const char* sc = smem + (c & 1) * STAGE;
#pragma unroll
        for (int s16 = 0; s16 < 2; s16++) {
            const int kk = s16 * 16 + lk2;
            uint32_t ah[2][4], al[2][4], bh[4][2], bl[4][2];
#pragma unroll
            for (int mt = 0; mt < 2; mt++) {
                int r0 = wm * 32 + mt * 16 + lq, r1 = r0 + 8;
                ah[mt][0] = lds32(sc + S_AH, r0, kk);
                ah[mt][1] = lds32(sc + S_AH, r1, kk);
                ah[mt][2] = lds32(sc + S_AH, r0, kk + 8);
                ah[mt][3] = lds32(sc + S_AH, r1, kk + 8);
                al[mt][0] = lds32(sc + S_AL, r0, kk);
                al[mt][1] = lds32(sc + S_AL, r1, kk);
                al[mt][2] = lds32(sc + S_AL, r0, kk + 8);
                al[mt][3] = lds32(sc + S_AL, r1, kk + 8);
            }
#pragma unroll
            for (int nt = 0; nt < 4; nt++) {
                int n = wn * 32 + nt * 8 + lq;
                bh[nt][0] = lds32(sc + S_BH, n, kk);
                bh[nt][1] = lds32(sc + S_BH, n, kk + 8);
                bl[nt][0] = lds32(sc + S_BL, n, kk);
                bl[nt][1] = lds32(sc + S_BL, n, kk + 8);
            }
#pragma unroll
            for (int mt = 0; mt < 2; mt++)
#pragma unroll
                for (int nt = 0; nt < 4; nt++) {
                    MMA16816(acc[mt][nt], ah[mt], bh[nt]);   // hi*hi
                    MMA16816(acc[mt][nt], al[mt], bh[nt]);   // lo*hi
                    MMA16816(acc[mt][nt], ah[mt], bl[nt]);   // hi*lo
                }
        }
        __syncthreads();
    }

    // ---- epilogue: direct stores (8-pixel-contiguous 32B sectors) ----
    const long long bOut = (long long)b * outBatchStride;
#pragma unroll
    for (int mt = 0; mt < 2; mt++)
#pragma unroll
        for (int nt = 0; nt < 4; nt++) {
            int m = pix0 + wm * 32 + mt * 16 + lq;
            int n = n0 + wn * 32 + nt * 8 + lk2;
            float* p = Out + bOut + (long long)n * NPIX + m;
            p[0]        = acc[mt][nt][0];
            p[NPIX]     = acc[mt][nt][1];
            p[8]        = acc[mt][nt][2];
            p[NPIX + 8] = acc[mt][nt][3];
        }
}

// ============================ split kernels =================================
__device__ __forceinline__ void split1(float v, __nv_bfloat16& h, __nv_bfloat16& l) {
    h = __float2bfloat16(v);
    l = __float2bfloat16(v - __bfloat162float(h));
}

__global__ void splitf4(const float* __restrict__ src, long long hoff, long long loff) {
    long long i = (long long)blockIdx.x * 256 + threadIdx.x;   // grid sized exactly
    float4 v = ((const float4*)src)[i];
    __nv_bfloat162 h0, h1, l0, l1;
    split1(v.x, h0.x, l0.x); split1(v.y, h0.y, l0.y);
    split1(v.z, h1.x, l1.x); split1(v.w, h1.y, l1.y);
    ((__nv_bfloat162*)(g_h + hoff))[2 * i]     = h0;
    ((__nv_bfloat162*)(g_h + hoff))[2 * i + 1] = h1;
    ((__nv_bfloat162*)(g_h + loff))[2 * i]     = l0;
    ((__nv_bfloat162*)(g_h + loff))[2 * i + 1] = l1;
}

__global__ void splitw(const float* __restrict__ src, long long hoff, long long loff, int n) {
    int i = blockIdx.x * 256 + threadIdx.x;
    if (i < n) {
        __nv_bfloat16 h, l; split1(src[i], h, l);
        g_h[hoff + i] = h; g_h[loff + i] = l;
    }
}

// q_w (out, cin, kh, kw) -> [tap][out][cin]
__global__ void splitqw(const float* __restrict__ qw) {
    int i = blockIdx.x * 256 + threadIdx.x;   // exactly 331776
    int o = i / 1728; int r = i - o * 1728; int ci = r / 9; int t = r - ci * 9;
    __nv_bfloat16 h, l; split1(qw[i], h, l);
    long long d = (long long)t * (192 * 192) + o * 192 + ci;
    g_h[QWH + d] = h; g_h[QWL + d] = l;
}

// ============================ depthwise 3x3 =================================
__global__ void dwconv(const float* __restrict__ wdw) {
    int bc = blockIdx.z;                       // b*2C + ch
    int b  = bc / (2 * C_);
    int ch = bc - b * 2 * C_;
    int h = blockIdx.y, w = threadIdx.x;
    const float* src = g_f + KV_OFF + (long long)bc * NPIX;

    float wv[9];
#pragma unroll
    for (int i = 0; i < 9; i++) wv[i] = __ldg(&wdw[ch * 9 + i]);

    float acc = 0.f;
#pragma unroll
    for (int kh = 0; kh < 3; kh++) {
        int hs = h + kh - 1;
        if (hs < 0 || hs >= H_) continue;
#pragma unroll
        for (int kw = 0; kw < 3; kw++) {
            int ws = w + kw - 1;
            if (ws < 0 || ws >= W_) continue;
            acc += wv[kh * 3 + kw] * src[hs * W_ + ws];
        }
    }
    long long p = (long long)h * W_ + w;
    if (ch < C_) {
        g_f[K2_OFF + ((long long)b * C_ + ch) * NPIX + p] = acc;   // k: fp32
    } else {
        __nv_bfloat16 hi, lo; split1(acc, hi, lo);                 // v: bf16 split
        long long o = ((long long)b * C_ + (ch - C_)) * NPIX + p;
        g_h[VH + o] = hi; g_h[VL + o] = lo;
    }
}

// ============================ norms / gram / softmax ========================
__global__ void sumsq() {
    int row = blockIdx.x;
    int isK = row >= B_ * C_;
    int r   = row - isK * (B_ * C_);
    const float* src = g_f + (isK ? K2_OFF : Q_OFF) + (long long)r * NPIX;
    float s = 0.f;
    for (int i = threadIdx.x; i < NPIX; i += 256) { float v = src[i]; s += v * v; }
    __shared__ float red[256];
    red[threadIdx.x] = s; __syncthreads();
    for (int st = 128; st > 0; st >>= 1) {
        if (threadIdx.x < st) red[threadIdx.x] += red[threadIdx.x + st];
        __syncthreads();
    }
    if (threadIdx.x == 0)
        g_f[(isK ? NK_OFF : NQ_OFF) + r] = fmaxf(sqrtf(red[0]), 1e-12f);
}

__global__ void zeroG() {
    g_f[G_OFF + (long long)blockIdx.x * 1024 + threadIdx.x] = 0.f;
}

__global__ void gram() {
    int bh = blockIdx.y;
    int b = bh / HEADS, hh = bh - b * HEADS;
    long long qbase = Q_OFF  + ((long long)b * C_ + hh * CPH) * NPIX;
    long long kbase = K2_OFF + ((long long)b * C_ + hh * CPH) * NPIX;
    int n0 = blockIdx.x * 1024;

    __shared__ float qs[CPH][33], ks[CPH][33];
    int tid = threadIdx.x;
    int c = tid >> 5, d = tid & 31;
    float acc = 0.f;
    for (int t = 0; t < 1024; t += 32) {
        qs[c][d] = g_f[qbase + (long long)c * NPIX + n0 + t + d];
        ks[c][d] = g_f[kbase + (long long)c * NPIX + n0 + t + d];
        __syncthreads();
#pragma unroll
        for (int j = 0; j < 32; j++) acc += qs[c][j] * ks[d][j];
        __syncthreads();
    }
    atomicAdd(&g_f[G_OFF + (long long)bh * 1024 + tid], acc);
}

__global__ void softmaxA(const float* __restrict__ temp) {
    int bh = blockIdx.x;
    int b = bh / HEADS, hh = bh - b * HEADS;
    int c = threadIdx.x;
    const float* G = g_f + G_OFF + (long long)bh * 1024;
    float*       A = g_f + AT_OFF + (long long)bh * 1024;
    float nq = g_f[NQ_OFF + b * C_ + hh * CPH + c];
    float t  = __ldg(&temp[hh]);
    float row[32]; float mx = -1e30f;
#pragma unroll
    for (int d = 0; d < 32; d++) {
        float nk = g_f[NK_OFF + b * C_ + hh * CPH + d];
        float v = G[c * 32 + d] / (nq * nk) * t;
        row[d] = v; mx = fmaxf(mx, v);
    }
    float sum = 0.f;
#pragma unroll
    for (int d = 0; d < 32; d++) { row[d] = __expf(row[d] - mx); sum += row[d]; }
    float inv = 1.f / sum;
#pragma unroll
    for (int d = 0; d < 32; d++) A[c * 32 + d] = row[d] * inv;
}

// M_b = proj_w @ blockdiag(A_b), written as bf16 hi/lo [b][out][cin]
__global__ void buildM(const float* __restrict__ projw) {
    int b = blockIdx.x, co = threadIdx.x;
    __shared__ float As_[HEADS * CPH * CPH];
    for (int i = co; i < HEADS * CPH * CPH; i += C_)
        As_[i] = g_f[AT_OFF + (long long)b * HEADS * CPH * CPH + i];
    __syncthreads();
    for (int hh = 0; hh < HEADS; hh++) {
        float p[CPH];
#pragma unroll
        for (int c = 0; c < CPH; c++) p[c] = __ldg(&projw[co * C_ + hh * CPH + c]);
        for (int d = 0; d < CPH; d++) {
            float s = 0.f;
#pragma unroll
            for (int c = 0; c < CPH; c++) s += p[c] * As_[hh * CPH * CPH + c * CPH + d];
            __nv_bfloat16 h, l; split1(s, h, l);
            long long o = ((long long)b * C_ + co) * C_ + hh * CPH + d;
            g_h[MWH + o] = h; g_h[MWL + o] = l;
        }
    }
}

// ============================ launch ========================================
extern "C" void kernel_launch(void* const* d_in, const int* in_sizes, int n_in,
                              void* d_out, int out_size)
{
    const float* x      = (const float*)d_in[0];
    const float* y      = (const float*)d_in[1];
    const float* q_w    = (const float*)d_in[2];
    const float* kv_w   = (const float*)d_in[3];
    const float* kvdw_w = (const float*)d_in[4];
    const float* proj_w = (const float*)d_in[5];
    const float* temp   = (const float*)d_in[6];
    float* out = (float*)d_out;
    (void)in_sizes; (void)n_in; (void)out_size;

    float* fbase = nullptr;
    __nv_bfloat16* hbase = nullptr;
    cudaGetSymbolAddress((void**)&fbase, g_f);
    cudaGetSymbolAddress((void**)&hbase, g_h);
    cudaFuncSetAttribute(hgemm, cudaFuncAttributeMaxDynamicSharedMemorySize, SMEM_TOTAL);

    zeroG<<<B_ * HEADS, 1024>>>();

    // split activations + weights to bf16 hi/lo
    splitf4<<<(int)(SACT / 4 / 256), 256>>>(x, XH, XL);
    splitf4<<<(int)(SACT / 4 / 256), 256>>>(y, YH, YL);
    splitw<<<(384 * 192 + 255) / 256, 256>>>(kv_w, KVWH, KVWL, 384 * 192);
    splitqw<<<192 * 1728 / 256, 256>>>(q_w);

    // kv = 1x1 conv(y): [384 x 192] GEMM
    hgemm<<<dim3(384 / 64, NPIX / 128, B_), 256, SMEM_TOTAL>>>(
        hbase + YH, hbase + YL, hbase + KVWH, hbase + KVWL, 0,
        fbase + KV_OFF, (long long)2 * C_ * NPIX, 384, 192, 1);

    // depthwise 3x3: k -> fp32, v -> bf16 split
    dwconv<<<dim3(1, H_, B_ * 2 * C_), W_>>>(kvdw_w);

    // q = 3x3 conv(x): 9 shifted GEMMs of K=192
    hgemm<<<dim3(192 / 64, NPIX / 128, B_), 256, SMEM_TOTAL>>>(
        hbase + XH, hbase + XL, hbase + QWH, hbase + QWL, 0,
        fbase + Q_OFF, (long long)C_ * NPIX, 192, 192, 9);

    // L2 norms of q and k rows
    sumsq<<<2 * B_ * C_, 256>>>();

    // Gram matrices q.k^T per (b, head)
    gram<<<dim3(NPIX / 1024, B_ * HEADS), 1024>>>();

    // normalize + temperature + softmax
    softmaxA<<<B_ * HEADS, CPH>>>(temp);

    // M_b = proj_w @ blockdiag(A_b)  (bf16 split output)
    buildM<<<B_, C_>>>(proj_w);

    // out = M_b @ v_b (fused attn@v + 1x1 proj)
    hgemm<<<dim3(192 / 64, NPIX / 128, B_), 256, SMEM_TOTAL>>>(
        hbase + VH, hbase + VL, hbase + MWH, hbase + MWL, (long long)C_ * C_,
        out, (long long)C_ * NPIX, 192, 192, 1);
}

// round 7
// speedup vs baseline: 2.4307x; 1.3704x over previous
#include <cuda_runtime.h>
#include <cuda_bf16.h>
#include <cstdint>
#include <math.h>

// ============================ problem constants =============================
constexpr int B_ = 4, C_ = 192, H_ = 192, W_ = 192;
constexpr int NPIX = H_ * W_;          // 36864
constexpr int HEADS = 6, CPH = 32;

// ============================ fp32 scratch ==================================
constexpr long long KV_OFF = 0;                                       // [B][2C][NPIX]
constexpr long long K2_OFF = KV_OFF + (long long)B_ * 2 * C_ * NPIX;  // k half [B][C][NPIX]
constexpr long long Q_OFF  = K2_OFF + (long long)B_ * C_ * NPIX;      // q (also v fp32 staging)
constexpr long long G_OFF  = Q_OFF  + (long long)B_ * C_ * NPIX;      // gram [24][1024]
constexpr long long AT_OFF = G_OFF  + B_ * HEADS * CPH * CPH;         // attn [24][1024]
constexpr long long NQ_OFF = AT_OFF + B_ * HEADS * CPH * CPH;
constexpr long long NK_OFF = NQ_OFF + B_ * C_;
constexpr long long FTOT   = NK_OFF + B_ * C_;
__device__ float g_f[FTOT];

// ============================ bf16 scratch (pixel-major acts) ===============
constexpr long long SACT = (long long)B_ * C_ * NPIX;   // 28,311,552
constexpr long long XH = 0,        XL = XH + SACT;
constexpr long long YH = XL + SACT, YL = YH + SACT;
constexpr long long VH = YL + SACT, VL = VH + SACT;
constexpr long long QWH  = VL + SACT;            // [9][192][192]
constexpr long long QWL  = QWH + 192 * 1728;
constexpr long long KVWH = QWL + 192 * 1728;     // [384][192]
constexpr long long KVWL = KVWH + 384 * 192;
constexpr long long MWH  = KVWL + 384 * 192;     // [B][192][192]
constexpr long long MWL  = MWH + (long long)B_ * C_ * C_;
constexpr long long HTOT = MWL + (long long)B_ * C_ * C_;
__device__ __align__(256) __nv_bfloat16 g_h[HTOT];

// ============================ PTX helpers ===================================
__device__ __forceinline__ uint32_t smem_u32(const void* p) {
    uint32_t a;
    asm("{ .reg .u64 t; cvta.to.shared.u64 t, %1; cvt.u32.u64 %0, t; }" : "=r"(a) : "l"(p));
    return a;
}
__device__ __forceinline__ void cp16(uint32_t sdst, const void* gsrc, int srcBytes) {
    asm volatile("cp.async.cg.shared.global [%0], [%1], 16, %2;"
                 :: "r"(sdst), "l"(gsrc), "r"(srcBytes));
}
#define CP_COMMIT() asm volatile("cp.async.commit_group;" ::: "memory")
#define CP_WAIT1()  asm volatile("cp.async.wait_group 1;" ::: "memory")
#define CP_WAIT0()  asm volatile("cp.async.wait_group 0;" ::: "memory")

__device__ __forceinline__ uint4 ldmx4(uint32_t addr) {
    uint4 r;
    asm volatile("ldmatrix.sync.aligned.m8n8.x4.shared.b16 {%0,%1,%2,%3}, [%4];"
                 : "=r"(r.x), "=r"(r.y), "=r"(r.z), "=r"(r.w) : "r"(addr));
    return r;
}
__device__ __forceinline__ void mma4(float* d, const uint4& a, uint32_t b0, uint32_t b1) {
    asm volatile("mma.sync.aligned.m16n8k16.row.col.f32.bf16.bf16.f32 "
                 "{%0,%1,%2,%3}, {%4,%5,%6,%7}, {%8,%9}, {%0,%1,%2,%3};"
                 : "+f"(d[0]), "+f"(d[1]), "+f"(d[2]), "+f"(d[3])
                 : "r"(a.x), "r"(a.y), "r"(a.z), "r"(a.w), "r"(b0), "r"(b1));
}

// ============================ warp MMA GEMM v2 ==============================
// D[128 pix, 64 out] = sum_taps sum_k A[b, pix+shift(tap), k] * W[tap, out, k]
// A pixel-major bf16 hi/lo [b][NPIX][192]; W [tap][outTot][192] hi/lo.
// smem rows padded to 80 B (5*16: 16B units of 8 rows hit distinct bank slots).
constexpr int ROWB = 80;
constexpr int S_AH = 0;
constexpr int S_AL = 128 * ROWB;                // 10240
constexpr int S_BH = 2 * 128 * ROWB;            // 20480
constexpr int S_BL = S_BH + 64 * ROWB;          // 25600
constexpr int STAGE = S_BL + 64 * ROWB;         // 30720
constexpr int SMEM_TOTAL = 2 * STAGE;           // 61440

__global__ void __launch_bounds__(256) hgemm(
    const __nv_bfloat16* __restrict__ Ahi, const __nv_bfloat16* __restrict__ Alo,
    const __nv_bfloat16* __restrict__ Whi, const __nv_bfloat16* __restrict__ Wlo,
    long long wBatchStride,
    float* __restrict__ Out, long long outBatchStride,
    int outTot, int ntaps)
{
    extern __shared__ char smem[];
    const uint32_t sb0 = smem_u32(smem);
    const int tid = threadIdx.x;
    const int lane = tid & 31, wid = tid >> 5;
    const int wm = wid & 3, wn = wid >> 2;          // warp grid 4(m) x 2(n)
    const int lq = lane >> 2, lk2 = (lane & 3) * 2;

    const int n0   = blockIdx.x * 64;
    const int pix0 = blockIdx.y * 128;
    const int b    = blockIdx.z;

    // ---- loader thread mapping ----
    const int arow = tid >> 1;                      // 0..127 (pixel row)
    const int au   = (tid & 1) * 2;                 // A 16B units au, au+1
    const int pgA  = pix0 + arow;
    const int phA  = pgA / W_, pwA = pgA - phA * W_;
    const int brow = tid >> 2;                      // 0..63 (out-ch row)
    const int bu   = tid & 3;

    const int nchunks = ntaps * 6;                  // 192/32 chunks per tap

    float acc[2][4][4];
#pragma unroll
    for (int i = 0; i < 2; i++)
#pragma unroll
        for (int j = 0; j < 4; j++)
#pragma unroll
            for (int r = 0; r < 4; r++) acc[i][j][r] = 0.f;

    auto load_stage = [&](int c, int buf) {
        int tap = (ntaps > 1) ? c / 6 : 0;
        int kc  = c - tap * 6;
        int k0  = kc * 32;
        int dh = 0, dw = 0;
        if (ntaps > 1) { dh = tap / 3 - 1; dw = tap - (tap / 3) * 3 - 1; }
        bool valid = ((unsigned)(phA + dh) < (unsigned)H_) &&
                     ((unsigned)(pwA + dw) < (unsigned)W_);
        int sz = valid ? 16 : 0;
        long long pix = valid ? (long long)(pgA + dh * W_ + dw) : (long long)pgA;
        long long ga  = ((long long)b * NPIX + pix) * 192 + k0 + au * 8;
        uint32_t sb = sb0 + buf * STAGE;
        uint32_t sa = sb + (uint32_t)(arow * ROWB + au * 16);
        cp16(sa,             Ahi + ga,     sz);
        cp16(sa + 16,        Ahi + ga + 8, sz);
        cp16(sa + S_AL,      Alo + ga,     sz);
        cp16(sa + S_AL + 16, Alo + ga + 8, sz);
        long long gb = (long long)b * wBatchStride +
                       ((long long)tap * outTot + n0 + brow) * 192 + k0 + bu * 8;
        uint32_t sw = sb + S_BH + (uint32_t)(brow * ROWB + bu * 16);
        cp16(sw,                 Whi + gb, 16);
        cp16(sw + (S_BL - S_BH), Wlo + gb, 16);
        CP_COMMIT();
    };

    // lane-level ldmatrix address offsets
    const uint32_t laneA = (uint32_t)(((lane & 7) + ((lane >> 3) & 1) * 8) * ROWB
                                      + (lane >> 4) * 16);
    const uint32_t laneB = (uint32_t)(((lane & 7) + (lane >> 4) * 8) * ROWB
                                      + ((lane >> 3) & 1) * 16);
    const uint32_t aoff = (uint32_t)(wm * 32 * ROWB);
    const uint32_t boff = (uint32_t)(wn * 32 * ROWB);

    load_stage(0, 0);

    for (int c = 0; c < nchunks; c++) {
        if (c + 1 < nchunks) { load_stage(c + 1, (c + 1) & 1); CP_WAIT1(); }
        else                 { CP_WAIT0(); }
        __syncthreads();

        const uint32_t sb = sb0 + (c & 1) * STAGE;
#pragma unroll
        for (int s16 = 0; s16 < 2; s16++) {
            uint32_t ka = sb + aoff + laneA + s16 * 32;
            uint4 ah0 = ldmx4(ka);
            uint4 ah1 = ldmx4(ka + 16 * ROWB);
            uint4 al0 = ldmx4(ka + S_AL);
            uint4 al1 = ldmx4(ka + S_AL + 16 * ROWB);
            uint32_t kb = sb + S_BH + boff + laneB + s16 * 32;
            uint4 bh0 = ldmx4(kb);                       // nt 0,1
            uint4 bh1 = ldmx4(kb + 16 * ROWB);           // nt 2,3
            uint4 bl0 = ldmx4(kb + (S_BL - S_BH));
            uint4 bl1 = ldmx4(kb + (S_BL - S_BH) + 16 * ROWB);

            uint32_t bhr[4][2] = {{bh0.x, bh0.y}, {bh0.z, bh0.w}, {bh1.x, bh1.y}, {bh1.z, bh1.w}};
            uint32_t blr[4][2] = {{bl0.x, bl0.y}, {bl0.z, bl0.w}, {bl1.x, bl1.y}, {bl1.z, bl1.w}};
#pragma unroll
            for (int nt = 0; nt < 4; nt++) {
                mma4(acc[0][nt], ah0, bhr[nt][0], bhr[nt][1]);
                mma4(acc[1][nt], ah1, bhr[nt][0], bhr[nt][1]);
                mma4(acc[0][nt], al0, bhr[nt][0], bhr[nt][1]);
                mma4(acc[1][nt], al1, bhr[nt][0], bhr[nt][1]);
                mma4(acc[0][nt], ah0, blr[nt][0], blr[nt][1]);
                mma4(acc[1][nt], ah1, blr[nt][0], blr[nt][1]);
            }
        }
        __syncthreads();
    }

    // ---- epilogue: direct stores (proven mapping from R6) ----
    const long long bOut = (long long)b * outBatchStride;
#pragma unroll
    for (int mt = 0; mt < 2; mt++)
#pragma unroll
        for (int nt = 0; nt < 4; nt++) {
            int m = pix0 + wm * 32 + mt * 16 + lq;
            int n = n0 + wn * 32 + nt * 8 + lk2;
            float* p = Out + bOut + (long long)n * NPIX + m;
            p[0]        = acc[mt][nt][0];
            p[NPIX]     = acc[mt][nt][1];
            p[8]        = acc[mt][nt][2];
            p[NPIX + 8] = acc[mt][nt][3];
        }
}

// ============================ split / transpose =============================
__device__ __forceinline__ void split1(float v, __nv_bfloat16& h, __nv_bfloat16& l) {
    h = __float2bfloat16(v);
    l = __float2bfloat16(v - __bfloat162float(h));
}

// [b][c][pix] fp32 -> pixel-major [b][pix][c] bf16 hi/lo (tiled transpose)
__global__ void splitT(const float* __restrict__ src, long long hoff, long long loff) {
    __shared__ float t[32][33];
    int pix0 = blockIdx.x * 32, c0 = blockIdx.y * 32, b = blockIdx.z;
    int tx = threadIdx.x, ty = threadIdx.y;       // 32 x 8
    const float* s = src + (long long)b * C_ * NPIX;
#pragma unroll
    for (int i = 0; i < 4; i++)
        t[ty + 8 * i][tx] = s[(long long)(c0 + ty + 8 * i) * NPIX + pix0 + tx];
    __syncthreads();
#pragma unroll
    for (int i = 0; i < 4; i++) {
        int p = ty + 8 * i;
        __nv_bfloat16 h, l; split1(t[tx][p], h, l);
        long long o = ((long long)b * NPIX + pix0 + p) * C_ + c0 + tx;
        g_h[hoff + o] = h; g_h[loff + o] = l;
    }
}

__global__ void splitw(const float* __restrict__ src, long long hoff, long long loff, int n) {
    int i = blockIdx.x * 256 + threadIdx.x;
    if (i < n) {
        __nv_bfloat16 h, l; split1(src[i], h, l);
        g_h[hoff + i] = h; g_h[loff + i] = l;
    }
}

// q_w (out, cin, kh, kw) -> [tap][out][cin]
__global__ void splitqw(const float* __restrict__ qw) {
    int i = blockIdx.x * 256 + threadIdx.x;       // exactly 331776
    int o = i / 1728; int r = i - o * 1728; int ci = r / 9; int t = r - ci * 9;
    __nv_bfloat16 h, l; split1(qw[i], h, l);
    long long d = (long long)t * (192 * 192) + o * 192 + ci;
    g_h[QWH + d] = h; g_h[QWL + d] = l;
}

// ============================ depthwise 3x3 =================================
__global__ void dwconv(const float* __restrict__ wdw) {
    int bc = blockIdx.z;                          // b*2C + ch
    int b  = bc / (2 * C_);
    int ch = bc - b * 2 * C_;
    int h = blockIdx.y, w = threadIdx.x;
    const float* src = g_f + KV_OFF + (long long)bc * NPIX;

    float wv[9];
#pragma unroll
    for (int i = 0; i < 9; i++) wv[i] = __ldg(&wdw[ch * 9 + i]);

    float acc = 0.f;
#pragma unroll
    for (int kh = 0; kh < 3; kh++) {
        int hs = h + kh - 1;
        if (hs < 0 || hs >= H_) continue;
#pragma unroll
        for (int kw = 0; kw < 3; kw++) {
            int ws = w + kw - 1;
            if (ws < 0 || ws >= W_) continue;
            acc += wv[kh * 3 + kw] * src[hs * W_ + ws];
        }
    }
    long long p = (long long)h * W_ + w;
    if (ch < C_)
        g_f[K2_OFF + ((long long)b * C_ + ch) * NPIX + p] = acc;       // k fp32
    else
        g_f[Q_OFF + ((long long)b * C_ + (ch - C_)) * NPIX + p] = acc; // v fp32 staging
}

// ============================ norms / gram / softmax ========================
__global__ void sumsq() {
    int row = blockIdx.x;
    int isK = row >= B_ * C_;
    int r   = row - isK * (B_ * C_);
    const float* src = g_f + (isK ? K2_OFF : Q_OFF) + (long long)r * NPIX;
    float s = 0.f;
    for (int i = threadIdx.x; i < NPIX; i += 256) { float v = src[i]; s += v * v; }
    __shared__ float red[256];
    red[threadIdx.x] = s; __syncthreads();
    for (int st = 128; st > 0; st >>= 1) {
        if (threadIdx.x < st) red[threadIdx.x] += red[threadIdx.x + st];
        __syncthreads();
    }
    if (threadIdx.x == 0)
        g_f[(isK ? NK_OFF : NQ_OFF) + r] = fmaxf(sqrtf(red[0]), 1e-12f);
}

__global__ void zeroG() {
    g_f[G_OFF + (long long)blockIdx.x * 1024 + threadIdx.x] = 0.f;
}

__global__ void gram() {
    int bh = blockIdx.y;
    int b = bh / HEADS, hh = bh - b * HEADS;
    long long qbase = Q_OFF  + ((long long)b * C_ + hh * CPH) * NPIX;
    long long kbase = K2_OFF + ((long long)b * C_ + hh * CPH) * NPIX;
    int n0 = blockIdx.x * 1024;

    __shared__ float qs[CPH][33], ks[CPH][33];
    int tid = threadIdx.x;
    int c = tid >> 5, d = tid & 31;
    float acc = 0.f;
    for (int t = 0; t < 1024; t += 32) {
        qs[c][d] = g_f[qbase + (long long)c * NPIX + n0 + t + d];
        ks[c][d] = g_f[kbase + (long long)c * NPIX + n0 + t + d];
        __syncthreads();
#pragma unroll
        for (int j = 0; j < 32; j++) acc += qs[c][j] * ks[d][j];
        __syncthreads();
    }
    atomicAdd(&g_f[G_OFF + (long long)bh * 1024 + tid], acc);
}

__global__ void softmaxA(const float* __restrict__ temp) {
    int bh = blockIdx.x;
    int b = bh / HEADS, hh = bh - b * HEADS;
    int c = threadIdx.x;
    const float* G = g_f + G_OFF + (long long)bh * 1024;
    float*       A = g_f + AT_OFF + (long long)bh * 1024;
    float nq = g_f[NQ_OFF + b * C_ + hh * CPH + c];
    float t  = __ldg(&temp[hh]);
    float row[32]; float mx = -1e30f;
#pragma unroll
    for (int d = 0; d < 32; d++) {
        float nk = g_f[NK_OFF + b * C_ + hh * CPH + d];
        float v = G[c * 32 + d] / (nq * nk) * t;
        row[d] = v; mx = fmaxf(mx, v);
    }
    float sum = 0.f;
#pragma unroll
    for (int d = 0; d < 32; d++) { row[d] = __expf(row[d] - mx); sum += row[d]; }
    float inv = 1.f / sum;
#pragma unroll
    for (int d = 0; d < 32; d++) A[c * 32 + d] = row[d] * inv;
}

// M_b = proj_w @ blockdiag(A_b), written as bf16 hi/lo [b][out][cin]
__global__ void buildM(const float* __restrict__ projw) {
    int b = blockIdx.x, co = threadIdx.x;
    __shared__ float As_[HEADS * CPH * CPH];
    for (int i = co; i < HEADS * CPH * CPH; i += C_)
        As_[i] = g_f[AT_OFF + (long long)b * HEADS * CPH * CPH + i];
    __syncthreads();
    for (int hh = 0; hh < HEADS; hh++) {
        float p[CPH];
#pragma unroll
        for (int c = 0; c < CPH; c++) p[c] = __ldg(&projw[co * C_ + hh * CPH + c]);
        for (int d = 0; d < CPH; d++) {
            float s = 0.f;
#pragma unroll
            for (int c = 0; c < CPH; c++) s += p[c] * As_[hh * CPH * CPH + c * CPH + d];
            __nv_bfloat16 h, l; split1(s, h, l);
            long long o = ((long long)b * C_ + co) * C_ + hh * CPH + d;
            g_h[MWH + o] = h; g_h[MWL + o] = l;
        }
    }
}

// ============================ launch ========================================
extern "C" void kernel_launch(void* const* d_in, const int* in_sizes, int n_in,
                              void* d_out, int out_size)
{
    const float* x      = (const float*)d_in[0];
    const float* y      = (const float*)d_in[1];
    const float* q_w    = (const float*)d_in[2];
    const float* kv_w   = (const float*)d_in[3];
    const float* kvdw_w = (const float*)d_in[4];
    const float* proj_w = (const float*)d_in[5];
    const float* temp   = (const float*)d_in[6];
    float* out = (float*)d_out;
    (void)in_sizes; (void)n_in; (void)out_size;

    float* fbase = nullptr;
    __nv_bfloat16* hbase = nullptr;
    cudaGetSymbolAddress((void**)&fbase, g_f);
    cudaGetSymbolAddress((void**)&hbase, g_h);
    cudaFuncSetAttribute(hgemm, cudaFuncAttributeMaxDynamicSharedMemorySize, SMEM_TOTAL);

    zeroG<<<B_ * HEADS, 1024>>>();

    // split+transpose activations; split weights
    splitT<<<dim3(NPIX / 32, C_ / 32, B_), dim3(32, 8)>>>(x, XH, XL);
    splitT<<<dim3(NPIX / 32, C_ / 32, B_), dim3(32, 8)>>>(y, YH, YL);
    splitw<<<(384 * 192 + 255) / 256, 256>>>(kv_w, KVWH, KVWL, 384 * 192);
    splitqw<<<192 * 1728 / 256, 256>>>(q_w);

    // kv = 1x1 conv(y)
    hgemm<<<dim3(384 / 64, NPIX / 128, B_), 256, SMEM_TOTAL>>>(
        hbase + YH, hbase + YL, hbase + KVWH, hbase + KVWL, 0,
        fbase + KV_OFF, (long long)2 * C_ * NPIX, 384, 1);

    // depthwise 3x3: k -> fp32 (K2), v -> fp32 staging (Q region)
    dwconv<<<dim3(1, H_, B_ * 2 * C_), W_>>>(kvdw_w);

    // v: fp32 staging -> pixel-major bf16 hi/lo
    splitT<<<dim3(NPIX / 32, C_ / 32, B_), dim3(32, 8)>>>(fbase + Q_OFF, VH, VL);

    // q = 3x3 conv(x): 9 shifted GEMMs (overwrites v staging in Q region)
    hgemm<<<dim3(192 / 64, NPIX / 128, B_), 256, SMEM_TOTAL>>>(
        hbase + XH, hbase + XL, hbase + QWH, hbase + QWL, 0,
        fbase + Q_OFF, (long long)C_ * NPIX, 192, 9);

    // L2 norms of q and k rows
    sumsq<<<2 * B_ * C_, 256>>>();

    // Gram matrices q.k^T per (b, head)
    gram<<<dim3(NPIX / 1024, B_ * HEADS), 1024>>>();

    // normalize + temperature + softmax
    softmaxA<<<B_ * HEADS, CPH>>>(temp);

    // M_b = proj_w @ blockdiag(A_b)
    buildM<<<B_, C_>>>(proj_w);

    // out = M_b @ v_b (fused attn@v + 1x1 proj)
    hgemm<<<dim3(192 / 64, NPIX / 128, B_), 256, SMEM_TOTAL>>>(
        hbase + VH, hbase + VL, hbase + MWH, hbase + MWL, (long long)C_ * C_,
        out, (long long)C_ * NPIX, 192, 1);
}